// round 1
// baseline (speedup 1.0000x reference)
#include <cuda_runtime.h>
#include <math.h>

// Problem constants
#define NB   2
#define NS   128
#define NROW (NB*NS)        // 256 rows (b*s)
#define NN   512            // feature dim
#define NM   1024           // 2*N output cols of GEMM
#define NK   512            // contraction dim

// Output layout (tuple concatenated): sample[131072] | mu[131072] | std_mat[67108864]
#define SAMPLE_ELEMS (NROW*NN)          // 131072
#define STD_ELEMS    ((long long)NROW*NN*NN) // 67108864

// Scratch (no allocations allowed)
__device__ float g_stats[NROW * NM];    // 1 MB
__device__ float g_var[NROW * NN];      // 0.5 MB

// ---------------- GEMM: C(256x1024) = A(256x512) * W^T(1024x512), + b ----------
#define BM 64
#define BN 64
#define BK 16

__global__ __launch_bounds__(256)
void gemm_kernel(const float* __restrict__ A, const float* __restrict__ W,
                 const float* __restrict__ bias, float* __restrict__ C) {
    __shared__ float As[BK][BM + 1];
    __shared__ float Bs[BK][BN + 1];

    const int tid = threadIdx.x;
    const int bx = blockIdx.x;   // N tile (0..15)
    const int by = blockIdx.y;   // M tile (0..3)
    const int ty = tid >> 4;     // 0..15
    const int tx = tid & 15;     // 0..15

    const int loadRow = tid >> 2;        // 0..63
    const int loadK4  = (tid & 3) << 2;  // 0,4,8,12

    const float* Ag = A + (size_t)(by * BM + loadRow) * NK;
    const float* Wg = W + (size_t)(bx * BN + loadRow) * NK;

    float acc[4][4] = {};

    for (int k0 = 0; k0 < NK; k0 += BK) {
        float4 a4 = *(const float4*)(Ag + k0 + loadK4);
        float4 w4 = *(const float4*)(Wg + k0 + loadK4);
        As[loadK4 + 0][loadRow] = a4.x;
        As[loadK4 + 1][loadRow] = a4.y;
        As[loadK4 + 2][loadRow] = a4.z;
        As[loadK4 + 3][loadRow] = a4.w;
        Bs[loadK4 + 0][loadRow] = w4.x;
        Bs[loadK4 + 1][loadRow] = w4.y;
        Bs[loadK4 + 2][loadRow] = w4.z;
        Bs[loadK4 + 3][loadRow] = w4.w;
        __syncthreads();

        #pragma unroll
        for (int kk = 0; kk < BK; kk++) {
            float a[4], w[4];
            #pragma unroll
            for (int i = 0; i < 4; i++) a[i] = As[kk][ty * 4 + i];
            #pragma unroll
            for (int j = 0; j < 4; j++) w[j] = Bs[kk][tx * 4 + j];
            #pragma unroll
            for (int i = 0; i < 4; i++)
                #pragma unroll
                for (int j = 0; j < 4; j++)
                    acc[i][j] = fmaf(a[i], w[j], acc[i][j]);
        }
        __syncthreads();
    }

    #pragma unroll
    for (int i = 0; i < 4; i++) {
        const int row = by * BM + ty * 4 + i;
        #pragma unroll
        for (int j = 0; j < 4; j++) {
            const int col = bx * BN + tx * 4 + j;
            C[(size_t)row * NM + col] = acc[i][j] + bias[col];
        }
    }
}

// ---------------- Pointwise: var/mu/sample ----------------
__device__ __forceinline__ float softplus_f(float x) {
    // numerically stable: max(x,0) + log1p(exp(-|x|))
    return fmaxf(x, 0.0f) + log1pf(expf(-fabsf(x)));
}

__global__ __launch_bounds__(256)
void pointwise_kernel(const float* __restrict__ stats,
                      const float* __restrict__ eps,
                      float* __restrict__ out_sample,
                      float* __restrict__ out_mu,
                      float* __restrict__ var_buf) {
    int idx = blockIdx.x * blockDim.x + threadIdx.x;
    if (idx >= SAMPLE_ELEMS) return;
    int row = idx >> 9;          // /512
    int i   = idx & (NN - 1);
    float s_var = stats[(size_t)row * NM + i];
    float s_mu  = stats[(size_t)row * NM + NN + i];
    float var = softplus_f(s_var);
    var_buf[idx]    = var;
    out_mu[idx]     = s_mu;
    out_sample[idx] = fmaf(sqrtf(var), eps[idx], s_mu);
}

// ---------------- Fill std_mat: zeros with diagonal = var ----------------
// std_mat is (NROW*NN) rows of NN floats; row r (global) has diagonal at col (r % NN).
__global__ __launch_bounds__(256)
void fill_std_kernel(const float* __restrict__ var_buf, float4* __restrict__ out4) {
    const long long total4 = STD_ELEMS >> 2;   // 16777216 float4 stores
    long long idx = (long long)blockIdx.x * blockDim.x + threadIdx.x;
    const long long stride = (long long)gridDim.x * blockDim.x;
    for (; idx < total4; idx += stride) {
        long long j = idx << 2;                // float index
        int r  = (int)(j >> 9);                // global row (0 .. 131071)
        int cs = (int)(j & (NN - 1));          // col start of this float4
        int d  = (r & (NN - 1)) - cs;          // diagonal offset within this float4
        float4 v = make_float4(0.f, 0.f, 0.f, 0.f);
        if ((unsigned)d < 4u) {
            float vv = var_buf[r];
            if      (d == 0) v.x = vv;
            else if (d == 1) v.y = vv;
            else if (d == 2) v.z = vv;
            else             v.w = vv;
        }
        out4[idx] = v;
    }
}

extern "C" void kernel_launch(void* const* d_in, const int* in_sizes, int n_in,
                              void* d_out, int out_size) {
    const float* x   = (const float*)d_in[0];
    const float* W   = (const float*)d_in[1];
    const float* b   = (const float*)d_in[2];
    const float* eps = (const float*)d_in[3];

    float* out        = (float*)d_out;
    float* out_sample = out;
    float* out_mu     = out + SAMPLE_ELEMS;
    float* out_std    = out + 2 * SAMPLE_ELEMS;

    float* stats;  cudaGetSymbolAddress((void**)&stats, g_stats);
    float* varb;   cudaGetSymbolAddress((void**)&varb,  g_var);

    // 1) GEMM -> stats scratch
    dim3 ggrid(NM / BN, NROW / BM);   // (16, 4)
    gemm_kernel<<<ggrid, 256>>>(x, W, b, stats);

    // 2) pointwise -> sample, mu, var scratch
    pointwise_kernel<<<SAMPLE_ELEMS / 256, 256>>>(stats, eps, out_sample, out_mu, varb);

    // 3) streaming fill of std_mat (zeros + diagonal)
    fill_std_kernel<<<8192, 256>>>(varb, (float4*)out_std);
}

// round 2
// speedup vs baseline: 1.3121x; 1.3121x over previous
#include <cuda_runtime.h>
#include <math.h>

// Problem constants
#define NB   2
#define NS   128
#define NROW (NB*NS)        // 256 rows (b*s)
#define NN   512            // feature dim
#define NM   1024           // 2*N output cols of GEMM
#define NK   512            // contraction dim

// Output layout (tuple concatenated): sample[131072] | mu[131072] | std_mat[67108864]
#define SAMPLE_ELEMS (NROW*NN)               // 131072
#define STD_ELEMS    ((long long)NROW*NN*NN) // 67108864

// Scratch (no allocations allowed)
__device__ float g_stats[NROW * NM];    // 1 MB
__device__ float g_var[NROW * NN];      // 0.5 MB

// ---------------- GEMM: C(256x1024) = A(256x512) * W^T(1024x512), + bias ------
// Tiles: 32(M) x 64(N) x 32(K) -> 8 x 16 = 128 CTAs (one full balanced wave).
#define GBM 32
#define GBN 64
#define GBK 32

__global__ __launch_bounds__(256)
void gemm_kernel(const float* __restrict__ A, const float* __restrict__ W,
                 const float* __restrict__ bias, float* __restrict__ C) {
    __shared__ float As[GBK][GBM + 1];
    __shared__ float Bs[GBK][GBN + 1];

    const int tid = threadIdx.x;
    const int bx = blockIdx.x;   // N tile (0..15)
    const int by = blockIdx.y;   // M tile (0..7)

    const int ty = tid >> 4;     // 0..15 -> rows ty*2 .. ty*2+1
    const int tx = tid & 15;     // cols tx*4 .. tx*4+3

    const int lr = tid >> 3;         // 0..31
    const int lk = (tid & 7) << 2;   // 0,4,...,28

    const float* Ag  = A + (size_t)(by * GBM + lr) * NK;
    const float* Wg0 = W + (size_t)(bx * GBN + lr) * NK;
    const float* Wg1 = Wg0 + (size_t)32 * NK;

    float acc[2][4] = {};

    for (int k0 = 0; k0 < NK; k0 += GBK) {
        float4 a4 = *(const float4*)(Ag  + k0 + lk);
        float4 b0 = *(const float4*)(Wg0 + k0 + lk);
        float4 b1 = *(const float4*)(Wg1 + k0 + lk);
        As[lk + 0][lr] = a4.x;
        As[lk + 1][lr] = a4.y;
        As[lk + 2][lr] = a4.z;
        As[lk + 3][lr] = a4.w;
        Bs[lk + 0][lr] = b0.x;
        Bs[lk + 1][lr] = b0.y;
        Bs[lk + 2][lr] = b0.z;
        Bs[lk + 3][lr] = b0.w;
        Bs[lk + 0][lr + 32] = b1.x;
        Bs[lk + 1][lr + 32] = b1.y;
        Bs[lk + 2][lr + 32] = b1.z;
        Bs[lk + 3][lr + 32] = b1.w;
        __syncthreads();

        #pragma unroll
        for (int kk = 0; kk < GBK; kk++) {
            float a0 = As[kk][ty * 2 + 0];
            float a1 = As[kk][ty * 2 + 1];
            float w0 = Bs[kk][tx * 4 + 0];
            float w1 = Bs[kk][tx * 4 + 1];
            float w2 = Bs[kk][tx * 4 + 2];
            float w3 = Bs[kk][tx * 4 + 3];
            acc[0][0] = fmaf(a0, w0, acc[0][0]);
            acc[0][1] = fmaf(a0, w1, acc[0][1]);
            acc[0][2] = fmaf(a0, w2, acc[0][2]);
            acc[0][3] = fmaf(a0, w3, acc[0][3]);
            acc[1][0] = fmaf(a1, w0, acc[1][0]);
            acc[1][1] = fmaf(a1, w1, acc[1][1]);
            acc[1][2] = fmaf(a1, w2, acc[1][2]);
            acc[1][3] = fmaf(a1, w3, acc[1][3]);
        }
        __syncthreads();
    }

    #pragma unroll
    for (int i = 0; i < 2; i++) {
        const int row = by * GBM + ty * 2 + i;
        #pragma unroll
        for (int j = 0; j < 4; j++) {
            const int col = bx * GBN + tx * 4 + j;
            C[(size_t)row * NM + col] = acc[i][j] + bias[col];
        }
    }
}

// ---------------- Pointwise: var/mu/sample ----------------
__device__ __forceinline__ float softplus_f(float x) {
    // numerically stable: max(x,0) + log1p(exp(-|x|))
    return fmaxf(x, 0.0f) + log1pf(expf(-fabsf(x)));
}

__global__ __launch_bounds__(256)
void pointwise_kernel(const float* __restrict__ stats,
                      const float* __restrict__ eps,
                      float* __restrict__ out_sample,
                      float* __restrict__ out_mu,
                      float* __restrict__ var_buf) {
    int idx = blockIdx.x * blockDim.x + threadIdx.x;
    if (idx >= SAMPLE_ELEMS) return;
    int row = idx >> 9;          // /512
    int i   = idx & (NN - 1);
    float s_var = stats[(size_t)row * NM + i];
    float s_mu  = stats[(size_t)row * NM + NN + i];
    float var = softplus_f(s_var);
    var_buf[idx]    = var;
    out_mu[idx]     = s_mu;
    out_sample[idx] = fmaf(sqrtf(var), eps[idx], s_mu);
}

// ---------------- Fill std_mat: zeros with diagonal = var ----------------
// std_mat is (NROW*NN) rows of NN floats; row r (global) has diagonal at col (r % NN).
__global__ __launch_bounds__(256)
void fill_std_kernel(const float* __restrict__ var_buf, float4* __restrict__ out4) {
    const long long total4 = STD_ELEMS >> 2;   // 16777216 float4 stores
    long long idx = (long long)blockIdx.x * blockDim.x + threadIdx.x;
    const long long stride = (long long)gridDim.x * blockDim.x;
    for (; idx < total4; idx += stride) {
        long long j = idx << 2;                // float index
        int r  = (int)(j >> 9);                // global row (0 .. 131071)
        int cs = (int)(j & (NN - 1));          // col start of this float4
        int d  = (r & (NN - 1)) - cs;          // diagonal offset within this float4
        float4 v = make_float4(0.f, 0.f, 0.f, 0.f);
        if ((unsigned)d < 4u) {
            float vv = var_buf[r];
            if      (d == 0) v.x = vv;
            else if (d == 1) v.y = vv;
            else if (d == 2) v.z = vv;
            else             v.w = vv;
        }
        __stcs(&out4[idx], v);   // evict-streaming: 256MB write-only stream
    }
}

extern "C" void kernel_launch(void* const* d_in, const int* in_sizes, int n_in,
                              void* d_out, int out_size) {
    const float* x   = (const float*)d_in[0];
    const float* W   = (const float*)d_in[1];
    const float* b   = (const float*)d_in[2];
    const float* eps = (const float*)d_in[3];

    float* out        = (float*)d_out;
    float* out_sample = out;
    float* out_mu     = out + SAMPLE_ELEMS;
    float* out_std    = out + 2 * SAMPLE_ELEMS;

    float* stats;  cudaGetSymbolAddress((void**)&stats, g_stats);
    float* varb;   cudaGetSymbolAddress((void**)&varb,  g_var);

    // 1) GEMM -> stats scratch (128 CTAs, one balanced wave)
    dim3 ggrid(NM / GBN, NROW / GBM);   // (16, 8)
    gemm_kernel<<<ggrid, 256>>>(x, W, b, stats);

    // 2) pointwise -> sample, mu, var scratch
    pointwise_kernel<<<SAMPLE_ELEMS / 256, 256>>>(stats, eps, out_sample, out_mu, varb);

    // 3) streaming fill of std_mat (zeros + diagonal)
    fill_std_kernel<<<8192, 256>>>(varb, (float4*)out_std);
}

// round 3
// speedup vs baseline: 1.4927x; 1.1377x over previous
#include <cuda_runtime.h>
#include <math.h>

// Problem constants
#define NB   2
#define NS   128
#define NROW (NB*NS)        // 256 rows (b*s)
#define NN   512            // feature dim
#define NM   1024           // 2*N output cols of GEMM
#define NK   512            // contraction dim

// Output layout (tuple concatenated): sample[131072] | mu[131072] | std_mat[67108864]
#define SAMPLE_ELEMS (NROW*NN)               // 131072
#define STD_ELEMS    ((long long)NROW*NN*NN) // 67108864

#define GBM 32
#define GBN 64
#define GBK 32
#define KS  4
#define KPER (NK/KS)        // 128
#define KITERS (KPER/GBK)   // 4

// Scratch (no allocations allowed)
__device__ float g_part[KS * NROW * NM];   // 4 MB of split-K partials
__device__ float g_var[NROW * NN];         // 0.5 MB

// ---------------- Split-K GEMM: P[z] = A(256x512[z-slice]) * W^T --------------
__global__ __launch_bounds__(256)
void gemm_kernel(const float* __restrict__ A, const float* __restrict__ W,
                 float* __restrict__ P) {
    __shared__ __align__(16) float As[2][GBK][GBM + 2];
    __shared__ __align__(16) float Bs[2][GBK][GBN + 4];

    const int tid = threadIdx.x;
    const int bx = blockIdx.x;   // N tile (0..15)
    const int by = blockIdx.y;   // M tile (0..7)
    const int bz = blockIdx.z;   // K split (0..3)

    const int ty = tid >> 4;     // 0..15 -> rows ty*2, ty*2+1
    const int tx = tid & 15;     // cols tx*4 .. tx*4+3

    const int lr = tid >> 3;         // 0..31
    const int lk = (tid & 7) << 2;   // 0,4,...,28

    const float* Ag  = A + (size_t)(by * GBM + lr) * NK + bz * KPER;
    const float* Wg0 = W + (size_t)(bx * GBN + lr) * NK + bz * KPER;
    const float* Wg1 = Wg0 + (size_t)32 * NK;

    float acc[2][4] = {};

    // Prologue: load tile 0 and stage into buffer 0
    float4 a4 = *(const float4*)(Ag  + lk);
    float4 b0 = *(const float4*)(Wg0 + lk);
    float4 b1 = *(const float4*)(Wg1 + lk);
    #pragma unroll
    for (int q = 0; q < 4; q++) {
        As[0][lk + q][lr]      = ((const float*)&a4)[q];
        Bs[0][lk + q][lr]      = ((const float*)&b0)[q];
        Bs[0][lk + q][lr + 32] = ((const float*)&b1)[q];
    }
    __syncthreads();

    int buf = 0;
    for (int it = 0; it < KITERS; it++) {
        float4 na, nb0, nb1;
        const bool more = (it + 1 < KITERS);
        if (more) {
            na  = *(const float4*)(Ag  + (it + 1) * GBK + lk);
            nb0 = *(const float4*)(Wg0 + (it + 1) * GBK + lk);
            nb1 = *(const float4*)(Wg1 + (it + 1) * GBK + lk);
        }

        #pragma unroll
        for (int kk = 0; kk < GBK; kk++) {
            float2 a2 = *(const float2*)&As[buf][kk][ty * 2];
            float4 w4 = *(const float4*)&Bs[buf][kk][tx * 4];
            acc[0][0] = fmaf(a2.x, w4.x, acc[0][0]);
            acc[0][1] = fmaf(a2.x, w4.y, acc[0][1]);
            acc[0][2] = fmaf(a2.x, w4.z, acc[0][2]);
            acc[0][3] = fmaf(a2.x, w4.w, acc[0][3]);
            acc[1][0] = fmaf(a2.y, w4.x, acc[1][0]);
            acc[1][1] = fmaf(a2.y, w4.y, acc[1][1]);
            acc[1][2] = fmaf(a2.y, w4.z, acc[1][2]);
            acc[1][3] = fmaf(a2.y, w4.w, acc[1][3]);
        }

        if (more) {
            const int nb = buf ^ 1;
            #pragma unroll
            for (int q = 0; q < 4; q++) {
                As[nb][lk + q][lr]      = ((const float*)&na)[q];
                Bs[nb][lk + q][lr]      = ((const float*)&nb0)[q];
                Bs[nb][lk + q][lr + 32] = ((const float*)&nb1)[q];
            }
            __syncthreads();
            buf = nb;
        }
    }

    // Epilogue: write partial (no bias here)
    float* Pp = P + (size_t)bz * (NROW * NM);
    #pragma unroll
    for (int i = 0; i < 2; i++) {
        const int row = by * GBM + ty * 2 + i;
        float4 v = make_float4(acc[i][0], acc[i][1], acc[i][2], acc[i][3]);
        *(float4*)(Pp + (size_t)row * NM + bx * GBN + tx * 4) = v;
    }
}

// ---------------- Pointwise: reduce split-K + var/mu/sample ----------------
__device__ __forceinline__ float softplus_f(float x) {
    return fmaxf(x, 0.0f) + log1pf(expf(-fabsf(x)));
}

__global__ __launch_bounds__(256)
void pointwise_kernel(const float* __restrict__ P,
                      const float* __restrict__ bias,
                      const float* __restrict__ eps,
                      float* __restrict__ out_sample,
                      float* __restrict__ out_mu,
                      float* __restrict__ var_buf) {
    int idx = blockIdx.x * blockDim.x + threadIdx.x;
    if (idx >= SAMPLE_ELEMS) return;
    int row = idx >> 9;          // /512
    int i   = idx & (NN - 1);

    float s_var = bias[i];
    float s_mu  = bias[NN + i];
    #pragma unroll
    for (int z = 0; z < KS; z++) {
        const float* Pz = P + (size_t)z * (NROW * NM) + (size_t)row * NM;
        s_var += Pz[i];
        s_mu  += Pz[NN + i];
    }
    float var = softplus_f(s_var);
    var_buf[idx]    = var;
    out_mu[idx]     = s_mu;
    out_sample[idx] = fmaf(sqrtf(var), eps[idx], s_mu);
}

// ---------------- Fill std_mat: zeros with diagonal = var ----------------
__global__ __launch_bounds__(256)
void fill_std_kernel(const float* __restrict__ var_buf, float4* __restrict__ out4) {
    const long long total4 = STD_ELEMS >> 2;   // 16777216 float4 stores
    long long idx = (long long)blockIdx.x * blockDim.x + threadIdx.x;
    const long long stride = (long long)gridDim.x * blockDim.x;
    for (; idx < total4; idx += stride) {
        long long j = idx << 2;                // float index
        int r  = (int)(j >> 9);                // global row (0 .. 131071)
        int cs = (int)(j & (NN - 1));          // col start of this float4
        int d  = (r & (NN - 1)) - cs;          // diagonal offset within this float4
        float4 v = make_float4(0.f, 0.f, 0.f, 0.f);
        if ((unsigned)d < 4u) {
            float vv = var_buf[r];
            if      (d == 0) v.x = vv;
            else if (d == 1) v.y = vv;
            else if (d == 2) v.z = vv;
            else             v.w = vv;
        }
        __stcs(&out4[idx], v);   // evict-streaming: 256MB write-only stream
    }
}

extern "C" void kernel_launch(void* const* d_in, const int* in_sizes, int n_in,
                              void* d_out, int out_size) {
    const float* x   = (const float*)d_in[0];
    const float* W   = (const float*)d_in[1];
    const float* b   = (const float*)d_in[2];
    const float* eps = (const float*)d_in[3];

    float* out        = (float*)d_out;
    float* out_sample = out;
    float* out_mu     = out + SAMPLE_ELEMS;
    float* out_std    = out + 2 * SAMPLE_ELEMS;

    float* part;  cudaGetSymbolAddress((void**)&part, g_part);
    float* varb;  cudaGetSymbolAddress((void**)&varb, g_var);

    // 1) Split-K GEMM -> partials (512 CTAs, 3-4 per SM)
    dim3 ggrid(NM / GBN, NROW / GBM, KS);   // (16, 8, 4)
    gemm_kernel<<<ggrid, 256>>>(x, W, part);

    // 2) pointwise reduce + sample/mu/var
    pointwise_kernel<<<SAMPLE_ELEMS / 256, 256>>>(part, b, eps, out_sample, out_mu, varb);

    // 3) streaming fill of std_mat (zeros + diagonal)
    fill_std_kernel<<<8192, 256>>>(varb, (float4*)out_std);
}